// round 10
// baseline (speedup 1.0000x reference)
#include <cuda_runtime.h>
#include <cstdint>

#define BATCH   4
#define NF      16
#define NC      8
#define NPIX    262144            // 512*512
#define DELTA_V 0.5f
#define CMAX    100000.0f

// K1 config (proven): 64 chunks per batch, 256 threads (4 fg x 2 pw warps)
#define CHUNKS    64
#define K1_THREADS 256
#define PAIRS_PER_CHUNK 2048      // (NPIX/2)/CHUNKS
#define K1_ITERS  32              // PAIRS_PER_CHUNK / 64 pixel-threads

// K3 config: 128 blocks/batch x 256 threads; 2048 px/block
#define K3_BLOCKS  128
#define K3_THREADS 256
#define K3_PX      2048
#define K3_ITERS   16             // 1024 pairs / 64 pixel-threads
#define TOTAL_K3   (BATCH * K3_BLOCKS)   // 512

typedef unsigned long long u64;

// ---- scratch (device globals; fully rewritten every launch) ----
__device__ float g_part1 [BATCH][CHUNKS][NF][NC];
__device__ float g_part1c[BATCH][CHUNKS][NC];
__device__ float g_part2 [TOTAL_K3];
__device__ unsigned g_fin_count = 0;

// ---- packed f32x2 helpers (Blackwell) ----
__device__ __forceinline__ u64 pack2(float lo, float hi) {
    u64 r; asm("mov.b64 %0, {%1, %2};" : "=l"(r) : "f"(lo), "f"(hi)); return r;
}
__device__ __forceinline__ void unpack2(u64 v, float& lo, float& hi) {
    asm("mov.b64 {%0, %1}, %2;" : "=f"(lo), "=f"(hi) : "l"(v));
}
__device__ __forceinline__ u64 fma2(u64 a, u64 b, u64 c) {
    u64 d; asm("fma.rn.f32x2 %0, %1, %2, %3;" : "=l"(d) : "l"(a), "l"(b), "l"(c)); return d;
}
__device__ __forceinline__ u64 add2(u64 a, u64 b) {
    u64 d; asm("add.rn.f32x2 %0, %1, %2;" : "=l"(d) : "l"(a), "l"(b)); return d;
}

// ============================================================================
// K1: masked per-class sums + counts (packed f32x2). Unchanged (near floor).
// ============================================================================
__global__ void __launch_bounds__(K1_THREADS)
k1_sums(const float* __restrict__ pred, const int* __restrict__ tgt)
{
    const int tid  = threadIdx.x;
    const int w    = tid >> 5;
    const int lane = tid & 31;
    const int fg   = w & 3;
    const int pw   = w >> 2;
    const int pl   = pw * 32 + lane;          // pixel-thread 0..63
    const int b    = blockIdx.y;

    const float* p0 = pred + (size_t)(b * NF + fg * 4) * NPIX;
    const int*   t0 = tgt  + (size_t)b * NPIX;
    const int basePair = blockIdx.x * PAIRS_PER_CHUNK;

    u64 acc[4][NC];
    u64 cnt[NC];
#pragma unroll
    for (int f = 0; f < 4; f++)
#pragma unroll
        for (int c = 0; c < NC; c++) acc[f][c] = 0ULL;
#pragma unroll
    for (int c = 0; c < NC; c++) cnt[c] = 0ULL;

    for (int i = 0; i < K1_ITERS; i++) {
        const int pair = basePair + i * 64 + pl;
        const int n0   = pair * 2;
        const int2 g   = *(const int2*)(t0 + n0);

        u64 m[NC];
#pragma unroll
        for (int c = 0; c < NC; c++)
            m[c] = pack2(g.x == c ? 1.0f : 0.0f, g.y == c ? 1.0f : 0.0f);

#pragma unroll
        for (int f = 0; f < 4; f++) {
            const u64 v = *(const u64*)(p0 + (size_t)f * NPIX + n0);
#pragma unroll
            for (int c = 0; c < NC; c++)
                acc[f][c] = fma2(v, m[c], acc[f][c]);
        }
        if (fg == 0) {
#pragma unroll
            for (int c = 0; c < NC; c++) cnt[c] = add2(cnt[c], m[c]);
        }
    }

#pragma unroll
    for (int f = 0; f < 4; f++)
#pragma unroll
        for (int c = 0; c < NC; c++)
            for (int o = 16; o > 0; o >>= 1)
                acc[f][c] = add2(acc[f][c], __shfl_xor_sync(0xffffffffu, acc[f][c], o));
    if (fg == 0) {
#pragma unroll
        for (int c = 0; c < NC; c++)
            for (int o = 16; o > 0; o >>= 1)
                cnt[c] = add2(cnt[c], __shfl_xor_sync(0xffffffffu, cnt[c], o));
    }

    __shared__ float s_s[4][2][4][NC];
    __shared__ float s_c[2][NC];
    if (lane == 0) {
#pragma unroll
        for (int f = 0; f < 4; f++)
#pragma unroll
            for (int c = 0; c < NC; c++) {
                float lo, hi; unpack2(acc[f][c], lo, hi);
                s_s[fg][pw][f][c] = lo + hi;
            }
        if (fg == 0) {
#pragma unroll
            for (int c = 0; c < NC; c++) {
                float lo, hi; unpack2(cnt[c], lo, hi);
                s_c[pw][c] = lo + hi;
            }
        }
    }
    __syncthreads();

    if (tid < 128) {
        const int fg2 = tid >> 5, f2 = (tid >> 3) & 3, c2 = tid & 7;
        __stcg(&g_part1[b][blockIdx.x][fg2 * 4 + f2][c2],
               s_s[fg2][0][f2][c2] + s_s[fg2][1][f2][c2]);
    }
    if (tid < NC)
        __stcg(&g_part1c[b][blockIdx.x][tid], s_c[0][tid] + s_c[1][tid]);
}

// ============================================================================
// K3: means -> warp-specialized variance pass (K1-shaped streams, packed
//     partial sq into SMEM) -> per-pixel combine -> last-block final
// ============================================================================
__global__ void __launch_bounds__(K3_THREADS)
k3_dist(const float* __restrict__ pred, const int* __restrict__ tgt,
        float* __restrict__ out)
{
    const int tid  = threadIdx.x;
    const int w    = tid >> 5;
    const int lane = tid & 31;
    const int fg   = w & 3;            // feature group (4 features)
    const int pw   = w >> 2;           // 0..1
    const int pl   = pw * 32 + lane;   // pixel-thread 0..63
    const int b    = blockIdx.y;
    const int blk  = blockIdx.x;

    __shared__ float  s_sq[4][K3_PX];    // 32 KB partial sq per fg per pixel
    __shared__ float  s_tmp[128][2];
    __shared__ float  s_ctmp[NC][2];
    __shared__ float  s_cnt[NC];
    __shared__ float4 s_m4[4][NC];       // [feature-group][class] -> 4 features
    __shared__ float  s_factor;
    __shared__ float  s_red[8];
    __shared__ float  s_f2[8];
    __shared__ unsigned s_last;

    // ---- means preamble (redundant per block, L2 reads) ----
    if (tid < 16) {
        const int c = tid >> 1, part = tid & 1;
        float s = 0.f;
#pragma unroll
        for (int i = 0; i < CHUNKS / 2; i++)
            s += __ldcg(&g_part1c[b][part * (CHUNKS / 2) + i][c]);
        s_ctmp[c][part] = s;
    }
    {
        const int idx = tid >> 1, part = tid & 1;   // idx = f*8+c
        const int f = idx >> 3, c = idx & 7;
        float s = 0.f;
#pragma unroll
        for (int i = 0; i < CHUNKS / 2; i++)
            s += __ldcg(&g_part1[b][part * (CHUNKS / 2) + i][f][c]);
        s_tmp[idx][part] = s;
    }
    __syncthreads();
    if (tid < NC)
        s_cnt[tid] = s_ctmp[tid][0] + s_ctmp[tid][1];
    __syncthreads();
    if (tid < 128) {
        const int f = tid >> 3, c = tid & 7;
        ((float*)&s_m4[f >> 2][c])[f & 3] = (s_tmp[tid][0] + s_tmp[tid][1]) / s_cnt[c];
    }
    if (tid == K3_THREADS - 1) {
        float fs = 0.f;
#pragma unroll
        for (int c = 0; c < NC; c++) fs += 1.0f / s_cnt[c];
        s_factor = fs * (1.0f / NC);
    }
    __syncthreads();

    // ---- phase 1: per-fg partial sq, K1-shaped (4 LDG.64 streams/thread) ----
    const float* p0 = pred + (size_t)(b * NF + fg * 4) * NPIX;
    const int*   t0 = tgt  + (size_t)b * NPIX;
    const int basePair = blk * (K3_PX / 2);
    const u64 NEG1 = pack2(-1.0f, -1.0f);

#pragma unroll 4
    for (int i = 0; i < K3_ITERS; i++) {
        const int lp = i * 64 + pl;          // local pair 0..1023
        const int n0 = (basePair + lp) * 2;
        const int2 g = *(const int2*)(t0 + n0);
        const float4 ma = s_m4[fg][g.x];
        const float4 mb = s_m4[fg][g.y];

        u64 sqp = 0ULL;
#pragma unroll
        for (int f = 0; f < 4; f++) {
            const u64 v  = *(const u64*)(p0 + (size_t)f * NPIX + n0);
            const u64 mp = pack2(((const float*)&ma)[f], ((const float*)&mb)[f]);
            const u64 d  = fma2(v, NEG1, mp);      // m - v (both pixels)
            sqp = fma2(d, d, sqp);
        }
        *(u64*)&s_sq[fg][lp * 2] = sqp;            // STS.64, conflict-free
    }
    __syncthreads();

    // ---- phase 2: combine 4 fg-partials per pixel, sqrt/clamp, reduce ----
    float local = 0.f;
#pragma unroll
    for (int k = 0; k < 2; k++) {
        const int px = k * 1024 + tid * 4;
        const float4 a0 = *(const float4*)&s_sq[0][px];
        const float4 a1 = *(const float4*)&s_sq[1][px];
        const float4 a2 = *(const float4*)&s_sq[2][px];
        const float4 a3 = *(const float4*)&s_sq[3][px];
        float s, dd, tt;
        s = (a0.x + a1.x) + (a2.x + a3.x);
        dd = sqrtf(s); tt = fminf(fmaxf(dd - DELTA_V, 0.f), CMAX); local = fmaf(tt, tt, local);
        s = (a0.y + a1.y) + (a2.y + a3.y);
        dd = sqrtf(s); tt = fminf(fmaxf(dd - DELTA_V, 0.f), CMAX); local = fmaf(tt, tt, local);
        s = (a0.z + a1.z) + (a2.z + a3.z);
        dd = sqrtf(s); tt = fminf(fmaxf(dd - DELTA_V, 0.f), CMAX); local = fmaf(tt, tt, local);
        s = (a0.w + a1.w) + (a2.w + a3.w);
        dd = sqrtf(s); tt = fminf(fmaxf(dd - DELTA_V, 0.f), CMAX); local = fmaf(tt, tt, local);
    }

    // block reduce (fixed order)
    for (int o = 16; o > 0; o >>= 1)
        local += __shfl_xor_sync(0xffffffffu, local, o);
    if (lane == 0) s_red[w] = local;
    __syncthreads();
    if (tid < 32) {
        float v = (tid < 8) ? s_red[tid] : 0.f;
        for (int o = 16; o > 0; o >>= 1)
            v += __shfl_xor_sync(0xffffffffu, v, o);
        if (tid == 0) __stcg(&g_part2[b * K3_BLOCKS + blk], v * s_factor);
    }

    // ---- last-block final reduction of 512 partials ----
    __syncthreads();
    if (tid == 0) {
        __threadfence();
        s_last = (atomicAdd(&g_fin_count, 1) == TOTAL_K3 - 1) ? 1u : 0u;
    }
    __syncthreads();
    if (s_last) {
        float v = __ldcg(&g_part2[tid]) + __ldcg(&g_part2[tid + 256]);
        for (int o = 16; o > 0; o >>= 1)
            v += __shfl_xor_sync(0xffffffffu, v, o);
        if (lane == 0) s_f2[w] = v;
        __syncthreads();
        if (tid == 0) {
            out[0] = ((s_f2[0] + s_f2[1]) + (s_f2[2] + s_f2[3]))
                   + ((s_f2[4] + s_f2[5]) + (s_f2[6] + s_f2[7]));
            g_fin_count = 0;   // reset for next graph replay
        }
    }
}

// ============================================================================
extern "C" void kernel_launch(void* const* d_in, const int* in_sizes, int n_in,
                              void* d_out, int out_size)
{
    const float* pred = (const float*)d_in[0];
    const int*   tgt  = (const int*)d_in[1];
    float* out = (float*)d_out;

    k1_sums<<<dim3(CHUNKS, BATCH), K1_THREADS>>>(pred, tgt);
    k3_dist<<<dim3(K3_BLOCKS, BATCH), K3_THREADS>>>(pred, tgt, out);
}